// round 2
// baseline (speedup 1.0000x reference)
#include <cuda_runtime.h>
#include <math.h>

// Problem shape (fixed by the dataset)
#define B_    32
#define S_    2048
#define ENC_  1024
#define DEC_  512
#define WROW  (ENC_ + DEC_)      // 1536, row stride of W
#define M_TOTAL (B_ * S_)        // 65536

// GEMM tiling
#define BM 128
#define BN 128
#define BK 16
// 256 threads = 16x16 thread grid, 8x8 micro-tile per thread

// Scratch (no allocations allowed): hproj and partial score planes
__device__ float g_hproj[B_ * DEC_];                    // 64 KB
__device__ float g_partial[(DEC_ / BN) * M_TOTAL];      // 4 * 65536 floats = 1 MB

// ---------------------------------------------------------------------------
// Kernel 1: h_proj[b][n] = bias[n] + sum_k hidden[b][k] * W[n][k]   (Wh part)
// ---------------------------------------------------------------------------
__global__ void hproj_kernel(const float* __restrict__ hidden,
                             const float* __restrict__ W,
                             const float* __restrict__ bvec) {
    __shared__ float hid[DEC_];
    const int b = blockIdx.x;
    const int n = threadIdx.x;           // 0..511
    hid[n] = hidden[b * DEC_ + n];
    __syncthreads();

    const float4* wrow = reinterpret_cast<const float4*>(W + (size_t)n * WROW);
    float acc = bvec[n];
#pragma unroll 8
    for (int k4 = 0; k4 < DEC_ / 4; k4++) {
        float4 w = wrow[k4];
        acc += hid[k4 * 4 + 0] * w.x;
        acc += hid[k4 * 4 + 1] * w.y;
        acc += hid[k4 * 4 + 2] * w.z;
        acc += hid[k4 * 4 + 3] * w.w;
    }
    g_hproj[b * DEC_ + n] = acc;
}

// ---------------------------------------------------------------------------
// Kernel 2: fused GEMM + tanh + v-dot partial reduction.
//   C[m][d] = sum_e enc[m][e] * We[d][e],  We[d][e] = W[d][DEC_ + e]
//   partial[nt][m] = sum_{d in tile nt} v[d] * tanh(C[m][d] + hproj[b(m)][d])
// Block = 128 (m) x 128 (d) tile, K loop over 1024 in steps of 16.
// ---------------------------------------------------------------------------
__global__ __launch_bounds__(256, 2)
void score_kernel(const float* __restrict__ enc,
                  const float* __restrict__ W,
                  const float* __restrict__ v) {
    __shared__ float As[BK][BM + 4];
    __shared__ float Bs[BK][BN + 4];
    __shared__ float red[16][BM];

    const int tid = threadIdx.x;
    const int tx  = tid & 15;
    const int ty  = tid >> 4;
    const int bm  = blockIdx.y * BM;     // row (b,s) offset; never spans batches
    const int bn  = blockIdx.x * BN;     // d offset
    const int batch = bm / S_;

    const float* Aptr = enc + (size_t)bm * ENC_;
    const float* Bptr = W + (size_t)bn * WROW + DEC_;   // We rows, stride WROW

    float acc[8][8];
#pragma unroll
    for (int i = 0; i < 8; i++)
#pragma unroll
        for (int j = 0; j < 8; j++) acc[i][j] = 0.f;

    for (int kt = 0; kt < ENC_; kt += BK) {
        // Load A and B tiles, transposed into smem (k-major)
#pragma unroll
        for (int l = 0; l < 2; l++) {
            int f   = tid + l * 256;        // 0..511
            int row = f >> 2;               // 0..127
            int kq  = (f & 3) << 2;         // 0,4,8,12
            float4 a = *reinterpret_cast<const float4*>(Aptr + (size_t)row * ENC_ + kt + kq);
            As[kq + 0][row] = a.x; As[kq + 1][row] = a.y;
            As[kq + 2][row] = a.z; As[kq + 3][row] = a.w;
            float4 bb = *reinterpret_cast<const float4*>(Bptr + (size_t)row * WROW + kt + kq);
            Bs[kq + 0][row] = bb.x; Bs[kq + 1][row] = bb.y;
            Bs[kq + 2][row] = bb.z; Bs[kq + 3][row] = bb.w;
        }
        __syncthreads();

#pragma unroll
        for (int kk = 0; kk < BK; kk++) {
            float4 a0 = *reinterpret_cast<const float4*>(&As[kk][ty * 8]);
            float4 a1 = *reinterpret_cast<const float4*>(&As[kk][ty * 8 + 4]);
            float4 b0 = *reinterpret_cast<const float4*>(&Bs[kk][tx * 8]);
            float4 b1 = *reinterpret_cast<const float4*>(&Bs[kk][tx * 8 + 4]);
            float af[8] = {a0.x, a0.y, a0.z, a0.w, a1.x, a1.y, a1.z, a1.w};
            float bf[8] = {b0.x, b0.y, b0.z, b0.w, b1.x, b1.y, b1.z, b1.w};
#pragma unroll
            for (int i = 0; i < 8; i++)
#pragma unroll
                for (int j = 0; j < 8; j++)
                    acc[i][j] += af[i] * bf[j];
        }
        __syncthreads();
    }

    // Epilogue: + hproj, tanh, * v, reduce over this block's 128 d-columns.
    float vv[8], hh[8];
#pragma unroll
    for (int j = 0; j < 8; j++) {
        int d = bn + tx * 8 + j;
        vv[j] = v[d];
        hh[j] = g_hproj[batch * DEC_ + d];
    }
    float p[8];
#pragma unroll
    for (int i = 0; i < 8; i++) {
        float s = 0.f;
#pragma unroll
        for (int j = 0; j < 8; j++)
            s += vv[j] * tanhf(acc[i][j] + hh[j]);
        p[i] = s;
    }
#pragma unroll
    for (int i = 0; i < 8; i++)
        red[tx][ty * 8 + i] = p[i];
    __syncthreads();

    if (tid < BM) {
        float s = 0.f;
#pragma unroll
        for (int t = 0; t < 16; t++) s += red[t][tid];
        g_partial[(size_t)blockIdx.x * M_TOTAL + bm + tid] = s;
    }
}

// ---------------------------------------------------------------------------
// Kernel 3: sum the 4 partial planes, softmax over S per batch.
// ---------------------------------------------------------------------------
__global__ void softmax_kernel(float* __restrict__ out) {
    __shared__ float sc[S_];
    __shared__ float redbuf[256];
    const int b   = blockIdx.x;
    const int tid = threadIdx.x;

    float lmax = -1e30f;
    for (int s0 = tid; s0 < S_; s0 += 256) {
        float sum = 0.f;
#pragma unroll
        for (int n = 0; n < DEC_ / BN; n++)
            sum += g_partial[(size_t)n * M_TOTAL + b * S_ + s0];
        sc[s0] = sum;
        lmax = fmaxf(lmax, sum);
    }
    redbuf[tid] = lmax;
    __syncthreads();
    for (int off = 128; off > 0; off >>= 1) {
        if (tid < off) redbuf[tid] = fmaxf(redbuf[tid], redbuf[tid + off]);
        __syncthreads();
    }
    const float m = redbuf[0];
    __syncthreads();

    float lsum = 0.f;
    for (int s0 = tid; s0 < S_; s0 += 256) {
        float e = expf(sc[s0] - m);
        sc[s0] = e;
        lsum += e;
    }
    redbuf[tid] = lsum;
    __syncthreads();
    for (int off = 128; off > 0; off >>= 1) {
        if (tid < off) redbuf[tid] += redbuf[tid + off];
        __syncthreads();
    }
    const float inv = 1.f / redbuf[0];
    __syncthreads();

    for (int s0 = tid; s0 < S_; s0 += 256)
        out[b * S_ + s0] = sc[s0] * inv;
}

// ---------------------------------------------------------------------------
extern "C" void kernel_launch(void* const* d_in, const int* in_sizes, int n_in,
                              void* d_out, int out_size) {
    const float* hidden = (const float*)d_in[0];   // (32, 512)
    const float* enc    = (const float*)d_in[1];   // (32, 2048, 1024)
    const float* W      = (const float*)d_in[2];   // (512, 1536)
    const float* bvec   = (const float*)d_in[3];   // (512,)
    const float* v      = (const float*)d_in[4];   // (512,)
    float* out          = (float*)d_out;           // (32, 1, 2048)

    hproj_kernel<<<B_, DEC_>>>(hidden, W, bvec);

    dim3 grid(DEC_ / BN, M_TOTAL / BM);            // (4, 512)
    score_kernel<<<grid, 256>>>(enc, W, v);

    softmax_kernel<<<B_, 256>>>(out);
}